// round 10
// baseline (speedup 1.0000x reference)
#include <cuda_runtime.h>
#include <cuda_bf16.h>
#include <float.h>
#include <stdint.h>

// ---------------- output layout (x_hat, idx, vq_loss, z_e) flattened fp32 ----
#define XHAT_OFF 0
#define IDX_OFF  1572864
#define LOSS_OFF 1574912
#define ZE_OFF   1574913

// ---------------- scratch ---------------------------------------------------
__device__ float g_h1[32*64*64*128];            // conv1 out fp32 channel-last [b][iy][ix][ic]
__device__ float g_pool[2048*128];              // pooled, layout [n][c]
__device__ float g_v[2048*128];                 // relu(dproj(z_q)) [n][oc]
__device__ float g_wprep[9*128*128];            // aggregated dconv1 weights [m][ic][oc]
__device__ float g_w2[36*4096];                 // conv2 W fp32 tiles, pre-swizzled [oc][32ch]
__device__ float g_partial[2048];               // per-position loss partials

// ---------------- helpers ----------------------------------------------------
__device__ __forceinline__ uint32_t smem_u32(const void* p) {
    uint32_t a;
    asm("{ .reg .u64 t; cvta.to.shared.u64 t, %1; cvt.u32.u64 %0, t; }"
        : "=r"(a) : "l"(p));
    return a;
}

#define SWZ128(o) ((o) ^ (((o) >> 3) & 0x70))

__device__ __forceinline__ uint32_t f2tf(float x) {
    uint32_t r;
    asm("cvt.rna.tf32.f32 %0, %1;" : "=r"(r) : "f"(x));
    return r;
}

__device__ __forceinline__ void mma_tf32(float* d, const uint32_t* a,
                                         uint32_t b0, uint32_t b1) {
    asm volatile(
        "mma.sync.aligned.m16n8k8.row.col.f32.tf32.tf32.f32 "
        "{%0,%1,%2,%3}, {%4,%5,%6,%7}, {%8,%9}, {%0,%1,%2,%3};"
        : "+f"(d[0]), "+f"(d[1]), "+f"(d[2]), "+f"(d[3])
        : "r"(a[0]), "r"(a[1]), "r"(a[2]), "r"(a[3]), "r"(b0), "r"(b1));
}

// ---------------- encoder conv1: (B,3,128,128) -> fp32 channel-last ----------
__global__ __launch_bounds__(128) void conv1_kernel(
    const float* __restrict__ x, const float* __restrict__ w,
    const float* __restrict__ bias)
{
    const int oc  = threadIdx.x;
    const int ox0 = blockIdx.x * 32;
    const int oy  = blockIdx.y;
    const int b   = blockIdx.z;
    __shared__ float s_in[3][3][66];
    __shared__ float s_out[128][33];

    for (int e = threadIdx.x; e < 3*3*66; e += 128) {
        int ic  = e / (3*66);
        int rem = e % (3*66);
        int ky  = rem / 66;
        int col = rem % 66;
        int ix  = 2*ox0 - 1 + col;
        int iy  = 2*oy  - 1 + ky;
        float v = 0.f;
        if (ix >= 0 && ix < 128 && iy >= 0 && iy < 128)
            v = x[((b*3 + ic)*128 + iy)*128 + ix];
        s_in[ic][ky][col] = v;
    }
    __syncthreads();

    float acc[32];
#pragma unroll
    for (int i = 0; i < 32; i++) acc[i] = 0.f;

#pragma unroll
    for (int ic = 0; ic < 3; ic++)
#pragma unroll
    for (int ky = 0; ky < 3; ky++)
#pragma unroll
    for (int kx = 0; kx < 3; kx++) {
        float wv = w[((oc*3 + ic)*3 + ky)*3 + kx];
#pragma unroll
        for (int ox = 0; ox < 32; ox++)
            acc[ox] = fmaf(wv, s_in[ic][ky][2*ox + kx], acc[ox]);
    }

    float bv = bias[oc];
#pragma unroll
    for (int ox = 0; ox < 32; ox++) {
        float v = acc[ox] + bv;
        s_out[oc][ox] = v > 0.f ? v : 0.f;
    }
    __syncthreads();
    // channel-last fp32: coalesced (consecutive tid -> consecutive channel)
    for (int e = threadIdx.x; e < 128*32; e += 128) {
        int o = e & 127, xw = e >> 7;
        g_h1[((b*64 + oy)*64 + (ox0 + xw))*128 + o] = s_out[o][xw];
    }
}

// ---------------- conv2 weight prep: fp32, pre-swizzled tile images ---------
// tile ti = tap*4 + (ic>>5): [128 oc rows][32 ch * 4B = 128B rows], SW128.
__global__ void w2prep_kernel(const float* __restrict__ w)
{
    int t = blockIdx.x*256 + threadIdx.x;
    if (t >= 128*128*9) return;
    int oc  = t & 127;
    int ic  = (t >> 7) & 127;
    int tap = t >> 14;
    float v = w[(oc*128 + ic)*9 + tap];
    int ti = tap*4 + (ic >> 5);
    uint32_t off = (uint32_t)(oc*128 + (ic & 31)*4);
    g_w2[ti*4096 + (SWZ128(off) >> 2)] = v;
}

// ---------------- conv2 via 3xTF32 mma.sync implicit GEMM + bias/ReLU/pool --
// CTA (g,b): M=128 positions (oy=4g..4g+3 x ox 0..31), N=128 oc.
// K = 9 taps x 4 ch-groups x 32 ch, split into tf32 hi/lo (3 terms).
// Double-buffered cp.async. Writes ONLY g_pool.
__global__ __launch_bounds__(256) void conv2_mma_kernel(const float* __restrict__ bias)
{
    extern __shared__ char smem[];
    const int g   = blockIdx.x;
    const int b   = blockIdx.y;
    const int tid = threadIdx.x;
    const int wid = tid >> 5, lane = tid & 31;
    const uint32_t sb = smem_u32(smem);
    // buffer k (k=0,1) at k*32768: A 16K | W 16K. bias at 67584.
    const uint32_t OFF_BIAS = 67584;

    if (tid < 128) ((float*)(smem + OFF_BIAS))[tid] = bias[tid];

    auto issue = [&](int it, int buf) {
        const uint32_t bb = sb + buf*32768;
        int tap = it >> 2, cg = it & 3;
        int ky = tap/3, kx = tap%3;
        // A tile: 1024 16B chunks (4 floats = 4 channels)
#pragma unroll
        for (int q = 0; q < 4; q++) {
            int cid = q*256 + tid;
            int row = cid >> 3, j = cid & 7;
            int iy = 2*(g*4 + (row >> 5)) - 1 + ky;
            int ix = 2*(row & 31) - 1 + kx;
            bool ok = (iy >= 0 && iy < 64 && ix >= 0 && ix < 64);
            const char* src = ok
                ? (const char*)(g_h1 + (((b*64 + iy)*64 + ix) << 7) + cg*32 + j*4)
                : (const char*)g_h1;
            uint32_t dst = bb + SWZ128((uint32_t)(row*128 + j*16));
            uint32_t sz  = ok ? 16u : 0u;
            asm volatile("cp.async.cg.shared.global [%0], [%1], 16, %2;"
                         :: "r"(dst), "l"(src), "r"(sz));
        }
        // W tile: pre-swizzled, linear copy (1024 chunks)
#pragma unroll
        for (int q = 0; q < 4; q++) {
            int cid = q*256 + tid;
            const char* src = (const char*)(g_w2 + it*4096) + cid*16;
            uint32_t dst = bb + 16384 + cid*16;
            asm volatile("cp.async.cg.shared.global [%0], [%1], 16;"
                         :: "r"(dst), "l"(src));
        }
        asm volatile("cp.async.commit_group;");
    };

    issue(0, 0);

    const int m0 = (wid >> 2)*64, n0 = (wid & 3)*32;
    float acc[4][4][4];
#pragma unroll
    for (int mt = 0; mt < 4; mt++)
#pragma unroll
        for (int nt = 0; nt < 4; nt++)
#pragma unroll
            for (int c = 0; c < 4; c++) acc[mt][nt][c] = 0.f;

    const int lr = lane >> 2, lc = lane & 3;

    for (int it = 0; it < 36; ++it) {
        if (it < 35) {
            issue(it + 1, (it + 1) & 1);
            asm volatile("cp.async.wait_group 1;");
        } else {
            asm volatile("cp.async.wait_group 0;");
        }
        __syncthreads();

        const uint32_t A = sb + (it & 1)*32768, W = A + 16384;

#pragma unroll
        for (int kk = 0; kk < 4; kk++) {
            // B fragments (W[n][k] layout == col-major KxN): split tf32 hi/lo
            uint32_t bh[4][2], bl[4][2];
#pragma unroll
            for (int nt = 0; nt < 4; nt++) {
                uint32_t r0 = (uint32_t)((n0 + nt*8 + lr)*128 + (kk*8 + lc)*4);
                float f0 = *(const float*)(smem + (W - sb) + SWZ128(r0));
                float f1 = *(const float*)(smem + (W - sb) + SWZ128(r0 + 16));
                uint32_t h0 = f2tf(f0), h1 = f2tf(f1);
                bh[nt][0] = h0; bh[nt][1] = h1;
                bl[nt][0] = f2tf(f0 - __uint_as_float(h0));
                bl[nt][1] = f2tf(f1 - __uint_as_float(h1));
            }
#pragma unroll
            for (int mt = 0; mt < 4; mt++) {
                uint32_t r0 = (uint32_t)((m0 + mt*16 + lr)*128 + (kk*8 + lc)*4);
                uint32_t r1 = r0 + 8*128;
                float a0 = *(const float*)(smem + (A - sb) + SWZ128(r0));
                float a1 = *(const float*)(smem + (A - sb) + SWZ128(r1));
                float a2 = *(const float*)(smem + (A - sb) + SWZ128(r0 + 16));
                float a3 = *(const float*)(smem + (A - sb) + SWZ128(r1 + 16));
                uint32_t ah[4], al[4];
                ah[0] = f2tf(a0); ah[1] = f2tf(a1); ah[2] = f2tf(a2); ah[3] = f2tf(a3);
                al[0] = f2tf(a0 - __uint_as_float(ah[0]));
                al[1] = f2tf(a1 - __uint_as_float(ah[1]));
                al[2] = f2tf(a2 - __uint_as_float(ah[2]));
                al[3] = f2tf(a3 - __uint_as_float(ah[3]));
#pragma unroll
                for (int nt = 0; nt < 4; nt++) {
                    mma_tf32(acc[mt][nt], ah, bh[nt][0], bh[nt][1]);
                    mma_tf32(acc[mt][nt], al, bh[nt][0], bh[nt][1]);
                    mma_tf32(acc[mt][nt], ah, bl[nt][0], bl[nt][1]);
                }
            }
        }
        __syncthreads();
    }

    // ---- epilogue: bias + ReLU -> smem [128 pos][132], then 4x4 pool -------
    float* sout = (float*)smem;                       // overlaps buffers (done)
    const float* sbias = (const float*)(smem + OFF_BIAS);
#pragma unroll
    for (int mt = 0; mt < 4; mt++)
#pragma unroll
        for (int nt = 0; nt < 4; nt++) {
            int row = m0 + mt*16 + lr;
            int col = n0 + nt*8 + 2*lc;
            float b0 = sbias[col], b1 = sbias[col + 1];
            float v0 = acc[mt][nt][0] + b0, v1 = acc[mt][nt][1] + b1;
            float v2 = acc[mt][nt][2] + b0, v3 = acc[mt][nt][3] + b1;
            float2* p0 = (float2*)&sout[row*132 + col];
            float2* p1 = (float2*)&sout[(row + 8)*132 + col];
            *p0 = make_float2(v0 > 0.f ? v0 : 0.f, v1 > 0.f ? v1 : 0.f);
            *p1 = make_float2(v2 > 0.f ? v2 : 0.f, v3 > 0.f ? v3 : 0.f);
        }
    __syncthreads();

#pragma unroll
    for (int q = 0; q < 4; q++) {
        int id = q*256 + tid;          // 1024 outputs: 8 gw x 128 oc
        int gw = id >> 7, oc = id & 127;
        float s = 0.f;
#pragma unroll
        for (int oyl = 0; oyl < 4; oyl++)
#pragma unroll
            for (int i = 0; i < 4; i++)
                s += sout[(oyl*32 + gw*4 + i)*132 + oc];
        g_pool[(b*64 + g*8 + gw)*128 + oc] = s * (1.f/16.f);
    }
}

// ---------------- proj + VQ + dproj fused, one block per grid cell ----------
__global__ __launch_bounds__(128) void projvq_kernel(
    const float* __restrict__ proj_w, const float* __restrict__ proj_b,
    const float* __restrict__ cb,
    const float* __restrict__ dproj_w, const float* __restrict__ dproj_b,
    float* __restrict__ out)
{
    int n = blockIdx.x;
    int b = n >> 6, gh = (n >> 3) & 7, gw = n & 7;
    int tid = threadIdx.x;
    __shared__ float s_pool[128];
    __shared__ float z[64];
    __shared__ float zq[64];
    __shared__ float red[128];
    __shared__ int   redi[128];

    s_pool[tid] = g_pool[n*128 + tid];
    __syncthreads();

    if (tid < 64) {
        float s = proj_b[tid];
        const float4* pw4 = reinterpret_cast<const float4*>(&proj_w[tid*128]);
#pragma unroll 8
        for (int c4 = 0; c4 < 32; c4++) {
            float4 wv = pw4[c4];
            s = fmaf(wv.x, s_pool[4*c4 + 0], s);
            s = fmaf(wv.y, s_pool[4*c4 + 1], s);
            s = fmaf(wv.z, s_pool[4*c4 + 2], s);
            s = fmaf(wv.w, s_pool[4*c4 + 3], s);
        }
        z[tid] = s;
        out[ZE_OFF + ((b*64 + tid)*8 + gh)*8 + gw] = s;
    }
    __syncthreads();

    float best = FLT_MAX; int bi = 0;
    for (int kk = 0; kk < 4; kk++) {
        int k = tid*4 + kk;
        const float4* ck4 = reinterpret_cast<const float4*>(&cb[k*64]);
        float d2 = 0.f;
#pragma unroll
        for (int q = 0; q < 16; q++) {
            float4 cv = ck4[q];
            float d0 = z[4*q + 0] - cv.x; d2 = fmaf(d0, d0, d2);
            float d1 = z[4*q + 1] - cv.y; d2 = fmaf(d1, d1, d2);
            float d3 = z[4*q + 2] - cv.z; d2 = fmaf(d3, d3, d2);
            float d4 = z[4*q + 3] - cv.w; d2 = fmaf(d4, d4, d2);
        }
        if (d2 < best) { best = d2; bi = k; }
    }
    red[tid] = best; redi[tid] = bi;
    __syncthreads();
    for (int s = 64; s > 0; s >>= 1) {
        if (tid < s) {
            float d2 = red[tid + s]; int k2 = redi[tid + s];
            if (d2 < red[tid] || (d2 == red[tid] && k2 < redi[tid])) {
                red[tid] = d2; redi[tid] = k2;
            }
        }
        __syncthreads();
    }
    int idx = redi[0];
    if (tid == 0) out[IDX_OFF + n] = (float)idx;
    if (tid < 64) zq[tid] = cb[idx*64 + tid];
    __syncthreads();

    if (tid < 64) { float df = zq[tid] - z[tid]; red[tid] = df*df; }
    __syncthreads();
    if (tid < 32) red[tid] += red[tid + 32];  __syncthreads();
    if (tid < 16) red[tid] += red[tid + 16];  __syncthreads();
    if (tid <  8) red[tid] += red[tid +  8];  __syncthreads();
    if (tid <  4) red[tid] += red[tid +  4];  __syncthreads();
    if (tid <  2) red[tid] += red[tid +  2];  __syncthreads();
    if (tid == 0) g_partial[n] = red[0] + red[1];

    float s2 = dproj_b[tid];
    const float4* dw4 = reinterpret_cast<const float4*>(&dproj_w[tid*64]);
#pragma unroll
    for (int q = 0; q < 16; q++) {
        float4 wv = dw4[q];
        s2 = fmaf(wv.x, zq[4*q + 0], s2);
        s2 = fmaf(wv.y, zq[4*q + 1], s2);
        s2 = fmaf(wv.z, zq[4*q + 2], s2);
        s2 = fmaf(wv.w, zq[4*q + 3], s2);
    }
    g_v[n*128 + tid] = s2 > 0.f ? s2 : 0.f;
}

// ---------------- loss reduce -----------------------------------------------
__global__ void loss_kernel(float* __restrict__ out)
{
    __shared__ float s[1024];
    int t = threadIdx.x;
    s[t] = g_partial[t] + g_partial[t + 1024];
    __syncthreads();
    for (int k = 512; k > 0; k >>= 1) {
        if (t < k) s[t] += s[t + k];
        __syncthreads();
    }
    if (t == 0) out[LOSS_OFF] = 1.25f * s[0] / (2048.f * 64.f);
}

// ---------------- aggregated dconv1 weights ---------------------------------
__global__ void wprep_kernel(const float* __restrict__ w)
{
    int t = blockIdx.x*128 + threadIdx.x;
    int oc = t & 127, ic = t >> 7;
    const float* wp = &w[(oc*128 + ic)*9];
    float W[9];
#pragma unroll
    for (int i = 0; i < 9; i++) W[i] = wp[i];
    float S  = W[0]+W[1]+W[2]+W[3]+W[4]+W[5]+W[6]+W[7]+W[8];
    float Rt = W[0]+W[1]+W[2];
    float Rb = W[6]+W[7]+W[8];
    float Cl = W[0]+W[3]+W[6];
    float Cr = W[2]+W[5]+W[8];
    float out9[9] = {S, Rt, Rb, Cl, Cr, W[0], W[2], W[6], W[8]};
#pragma unroll
    for (int m = 0; m < 9; m++)
        g_wprep[(m*128 + ic)*128 + oc] = out9[m];
}

// ---------------- decoder: block-structured dconv1 + ReLU + dconv2 ----------
__global__ __launch_bounds__(128) void dec_kernel(
    const float* __restrict__ b1, const float* __restrict__ w2,
    const float* __restrict__ b2, float* __restrict__ out)
{
    int n0  = blockIdx.x * 4;
    int tid = threadIdx.x;
    __shared__ float s_comb[4][9][128];
    __shared__ float s_hcat[4][9][128];
    __shared__ float s_rgb[4][27];

#pragma unroll
    for (int cell = 0; cell < 4; cell++) {
        int n = n0 + cell;
        int gh = (n >> 3) & 7, gw = n & 7;
        float v00 = g_v[n*128 + tid];
        float va  = gh > 0             ? g_v[(n-8)*128 + tid] : 0.f;
        float vb  = gh < 7             ? g_v[(n+8)*128 + tid] : 0.f;
        float vl  = gw > 0             ? g_v[(n-1)*128 + tid] : 0.f;
        float vr  = gw < 7             ? g_v[(n+1)*128 + tid] : 0.f;
        float vtl = (gh > 0 && gw > 0) ? g_v[(n-9)*128 + tid] : 0.f;
        float vtr = (gh > 0 && gw < 7) ? g_v[(n-7)*128 + tid] : 0.f;
        float vbl = (gh < 7 && gw > 0) ? g_v[(n+7)*128 + tid] : 0.f;
        float vbr = (gh < 7 && gw < 7) ? g_v[(n+9)*128 + tid] : 0.f;

        s_comb[cell][0][tid] = v00;
        s_comb[cell][1][tid] = va - v00;
        s_comb[cell][2][tid] = vb - v00;
        s_comb[cell][3][tid] = vl - v00;
        s_comb[cell][4][tid] = vr - v00;
        s_comb[cell][5][tid] = vtl - va - vl + v00;
        s_comb[cell][6][tid] = vtr - va - vr + v00;
        s_comb[cell][7][tid] = vbl - vb - vl + v00;
        s_comb[cell][8][tid] = vbr - vb - vr + v00;
    }
    __syncthreads();

    float a[4][9];
#pragma unroll
    for (int cell = 0; cell < 4; cell++)
#pragma unroll
        for (int m = 0; m < 9; m++) a[cell][m] = 0.f;

    for (int ic = 0; ic < 128; ic++) {
#pragma unroll
        for (int m = 0; m < 9; m++) {
            float wv = g_wprep[(m*128 + ic)*128 + tid];
#pragma unroll
            for (int cell = 0; cell < 4; cell++)
                a[cell][m] = fmaf(wv, s_comb[cell][m][ic], a[cell][m]);
        }
    }

    float bv = b1[tid];
#pragma unroll
    for (int cell = 0; cell < 4; cell++) {
        float base = a[cell][0] + bv;
        float hm[9];
        hm[4] = base;
        hm[1] = base + a[cell][1];
        hm[7] = base + a[cell][2];
        hm[3] = base + a[cell][3];
        hm[5] = base + a[cell][4];
        hm[0] = base + a[cell][1] + a[cell][3] + a[cell][5];
        hm[2] = base + a[cell][1] + a[cell][4] + a[cell][6];
        hm[6] = base + a[cell][2] + a[cell][3] + a[cell][7];
        hm[8] = base + a[cell][2] + a[cell][4] + a[cell][8];
#pragma unroll
        for (int c = 0; c < 9; c++)
            s_hcat[cell][c][tid] = hm[c] > 0.f ? hm[c] : 0.f;
    }
    __syncthreads();

    if (tid < 108) {
        int cell = tid / 27;
        int r    = tid % 27;
        int ch   = r / 9;
        int cat  = r % 9;
        const float4* wc4 = reinterpret_cast<const float4*>(&w2[ch*128]);
        const float*  hc  = &s_hcat[cell][cat][0];
        float s = 0.f;
#pragma unroll
        for (int q = 0; q < 32; q++) {
            float4 wv = wc4[q];
            s = fmaf(wv.x, hc[4*q + 0], s);
            s = fmaf(wv.y, hc[4*q + 1], s);
            s = fmaf(wv.z, hc[4*q + 2], s);
            s = fmaf(wv.w, hc[4*q + 3], s);
        }
        s_rgb[cell][r] = s + b2[ch];
    }
    __syncthreads();

    for (int p = tid; p < 3072; p += 128) {
        int cell = p / 768;
        int rem  = p % 768;
        int ch = rem >> 8, r = (rem >> 4) & 15, c = rem & 15;
        int n = n0 + cell;
        int b = n >> 6, gh = (n >> 3) & 7, gw = n & 7;
        int rcat = (r == 0) ? 0 : ((r == 15) ? 2 : 1);
        int ccat = (c == 0) ? 0 : ((c == 15) ? 2 : 1);
        out[XHAT_OFF + ((b*3 + ch)*128 + gh*16 + r)*128 + gw*16 + c]
            = s_rgb[cell][ch*9 + rcat*3 + ccat];
    }
}

// ---------------- launch ----------------------------------------------------
extern "C" void kernel_launch(void* const* d_in, const int* in_sizes, int n_in,
                              void* d_out, int out_size)
{
    const float* x        = (const float*)d_in[0];
    const float* enc_w1   = (const float*)d_in[1];
    const float* enc_b1   = (const float*)d_in[2];
    const float* enc_w2   = (const float*)d_in[3];
    const float* enc_b2   = (const float*)d_in[4];
    const float* proj_w   = (const float*)d_in[5];
    const float* proj_b   = (const float*)d_in[6];
    const float* codebook = (const float*)d_in[7];
    const float* dproj_w  = (const float*)d_in[8];
    const float* dproj_b  = (const float*)d_in[9];
    const float* dconv1_w = (const float*)d_in[10];
    const float* dconv1_b = (const float*)d_in[11];
    const float* dconv2_w = (const float*)d_in[12];
    const float* dconv2_b = (const float*)d_in[13];
    float* out = (float*)d_out;

    cudaFuncSetAttribute(conv2_mma_kernel,
                         cudaFuncAttributeMaxDynamicSharedMemorySize, 68096);

    conv1_kernel<<<dim3(2, 64, 32), 128>>>(x, enc_w1, enc_b1);
    w2prep_kernel<<<576, 256>>>(enc_w2);
    wprep_kernel<<<128, 128>>>(dconv1_w);
    conv2_mma_kernel<<<dim3(8, 32), 256, 68096>>>(enc_b2);
    projvq_kernel<<<2048, 128>>>(proj_w, proj_b, codebook, dproj_w, dproj_b, out);
    loss_kernel<<<1, 1024>>>(out);
    dec_kernel<<<512, 128>>>(dconv1_b, dconv2_w, dconv2_b, out);
}

// round 12
// speedup vs baseline: 1.4936x; 1.4936x over previous
#include <cuda_runtime.h>
#include <cuda_bf16.h>
#include <float.h>
#include <stdint.h>

// ---------------- output layout (x_hat, idx, vq_loss, z_e) flattened fp32 ----
#define XHAT_OFF 0
#define IDX_OFF  1572864
#define LOSS_OFF 1574912
#define ZE_OFF   1574913

// ---------------- scratch ---------------------------------------------------
// conv1 out, tf32-rounded hi/lo planes, channel-last with PAIR PERMUTATION:
// within each 8-channel group, logical ch c stored at (c&3)*2 + (c>>2 & 1)
// so k-pairs (c, c+4) are adjacent for LDS.64 fragment loads.
__device__ float g_h1h[32*64*64*128];
__device__ float g_h1l[32*64*64*128];
__device__ float g_pool[2048*128];              // pooled, layout [n][c]
__device__ float g_v[2048*128];                 // relu(dproj(z_q)) [n][oc]
__device__ float g_wprep[9*128*128];            // aggregated dconv1 weights [m][ic][oc]
// conv2 W tiles: [36 tiles][128 oc rows x 40 floats (160B pitch, 32 perm ch)]
__device__ float g_w2h[36*5120];
__device__ float g_w2l[36*5120];
__device__ float g_partial[2048];               // per-position loss partials

// ---------------- helpers ----------------------------------------------------
__device__ __forceinline__ uint32_t smem_u32(const void* p) {
    uint32_t a;
    asm("{ .reg .u64 t; cvta.to.shared.u64 t, %1; cvt.u32.u64 %0, t; }"
        : "=r"(a) : "l"(p));
    return a;
}

__device__ __forceinline__ uint32_t f2tf(float x) {
    uint32_t r;
    asm("cvt.rna.tf32.f32 %0, %1;" : "=r"(r) : "f"(x));
    return r;
}

__device__ __forceinline__ void mma_tf32(float* d, const uint32_t* a,
                                         uint32_t b0, uint32_t b1) {
    asm volatile(
        "mma.sync.aligned.m16n8k8.row.col.f32.tf32.tf32.f32 "
        "{%0,%1,%2,%3}, {%4,%5,%6,%7}, {%8,%9}, {%0,%1,%2,%3};"
        : "+f"(d[0]), "+f"(d[1]), "+f"(d[2]), "+f"(d[3])
        : "r"(a[0]), "r"(a[1]), "r"(a[2]), "r"(a[3]), "r"(b0), "r"(b1));
}

// ---------------- encoder conv1: (B,3,128,128) -> tf32 hi/lo channel-last ----
__global__ __launch_bounds__(128) void conv1_kernel(
    const float* __restrict__ x, const float* __restrict__ w,
    const float* __restrict__ bias)
{
    const int oc  = threadIdx.x;
    const int ox0 = blockIdx.x * 32;
    const int oy  = blockIdx.y;
    const int b   = blockIdx.z;
    __shared__ float s_in[3][3][66];
    __shared__ float s_out[128][33];

    for (int e = threadIdx.x; e < 3*3*66; e += 128) {
        int ic  = e / (3*66);
        int rem = e % (3*66);
        int ky  = rem / 66;
        int col = rem % 66;
        int ix  = 2*ox0 - 1 + col;
        int iy  = 2*oy  - 1 + ky;
        float v = 0.f;
        if (ix >= 0 && ix < 128 && iy >= 0 && iy < 128)
            v = x[((b*3 + ic)*128 + iy)*128 + ix];
        s_in[ic][ky][col] = v;
    }
    __syncthreads();

    float acc[32];
#pragma unroll
    for (int i = 0; i < 32; i++) acc[i] = 0.f;

#pragma unroll
    for (int ic = 0; ic < 3; ic++)
#pragma unroll
    for (int ky = 0; ky < 3; ky++)
#pragma unroll
    for (int kx = 0; kx < 3; kx++) {
        float wv = w[((oc*3 + ic)*3 + ky)*3 + kx];
#pragma unroll
        for (int ox = 0; ox < 32; ox++)
            acc[ox] = fmaf(wv, s_in[ic][ky][2*ox + kx], acc[ox]);
    }

    float bv = bias[oc];
#pragma unroll
    for (int ox = 0; ox < 32; ox++) {
        float v = acc[ox] + bv;
        s_out[oc][ox] = v > 0.f ? v : 0.f;
    }
    __syncthreads();
    for (int e = threadIdx.x; e < 128*32; e += 128) {
        int o = e & 127, xw = e >> 7;
        float v = s_out[o][xw];
        float hv = __uint_as_float(f2tf(v));
        float lv = __uint_as_float(f2tf(v - hv));
        int p = (o & ~7) | ((o & 3) << 1) | ((o >> 2) & 1);   // pair permutation
        int idx = ((b*64 + oy)*64 + (ox0 + xw))*128 + p;
        g_h1h[idx] = hv;
        g_h1l[idx] = lv;
    }
}

// ---------------- prep: conv2 W tiles (tf32 hi/lo, permuted, 160B pitch)
//                  + aggregated dconv1 weights -------------------------------
__global__ void prep_kernel(const float* __restrict__ w2,
                            const float* __restrict__ w1d)
{
    int t = blockIdx.x*256 + threadIdx.x;
    if (t < 147456) {
        int oc  = t & 127;
        int ic  = (t >> 7) & 127;
        int tap = t >> 14;
        float v = w2[(oc*128 + ic)*9 + tap];
        float hv = __uint_as_float(f2tf(v));
        float lv = __uint_as_float(f2tf(v - hv));
        int ti   = tap*4 + (ic >> 5);
        int sub8 = (ic >> 3) & 3;
        int w8   = ic & 7;
        int coff = sub8*8 + ((w8 & 3) << 1) + (w8 >> 2);
        g_w2h[ti*5120 + oc*40 + coff] = hv;
        g_w2l[ti*5120 + oc*40 + coff] = lv;
    }
    if (t < 16384) {
        int oc = t & 127, ic = t >> 7;
        const float* wp = &w1d[(oc*128 + ic)*9];
        float W[9];
#pragma unroll
        for (int i = 0; i < 9; i++) W[i] = wp[i];
        float S  = W[0]+W[1]+W[2]+W[3]+W[4]+W[5]+W[6]+W[7]+W[8];
        float Rt = W[0]+W[1]+W[2];
        float Rb = W[6]+W[7]+W[8];
        float Cl = W[0]+W[3]+W[6];
        float Cr = W[2]+W[5]+W[8];
        float out9[9] = {S, Rt, Rb, Cl, Cr, W[0], W[2], W[6], W[8]};
#pragma unroll
        for (int m = 0; m < 9; m++)
            g_wprep[(m*128 + ic)*128 + oc] = out9[m];
    }
}

// ---------------- conv2 via 3xTF32 mma.sync implicit GEMM + bias/ReLU/pool --
// CTA (g,b): M=128 positions (oy=4g..4g+3 x ox 0..31), N=128 oc.
// Planes precomputed tf32 hi/lo -> zero conversions in mainloop.
// Tiles: 128 rows x 160B pitch (32 permuted ch) -> conflict-free LDS.64 frags.
// Stage = 4 planes x 20KB = 80KB, double buffered. Writes ONLY g_pool.
__global__ __launch_bounds__(256, 1) void conv2_mma_kernel(const float* __restrict__ bias)
{
    extern __shared__ char smem[];
    const int g   = blockIdx.x;
    const int b   = blockIdx.y;
    const int tid = threadIdx.x;
    const int wid = tid >> 5, lane = tid & 31;
    const uint32_t sb = smem_u32(smem);
    const uint32_t STG = 81920;          // per-stage: Ah|Al|Wh|Wl (20480 each)
    const uint32_t OFF_BIAS = 163840;

    if (tid < 128) ((float*)(smem + OFF_BIAS))[tid] = bias[tid];

    auto issue = [&](int it, int buf) {
        const uint32_t bb = sb + buf*STG;
        int tap = it >> 2, cg = it & 3;
        int ky = tap/3, kx = tap%3;
        // A planes: 2048 chunks (hi 1024 + lo 1024)
#pragma unroll
        for (int q = 0; q < 8; q++) {
            int cid = q*256 + tid;
            int pl  = cid >> 10;
            int r   = (cid >> 3) & 127;
            int j   = cid & 7;
            int iy = 2*(g*4 + (r >> 5)) - 1 + ky;
            int ix = 2*(r & 31) - 1 + kx;
            bool ok = (iy >= 0 && iy < 64 && ix >= 0 && ix < 64);
            const float* base = pl ? g_h1l : g_h1h;
            const char* src = ok
                ? (const char*)(base + (((b*64 + iy)*64 + ix) << 7) + cg*32 + j*4)
                : (const char*)base;
            uint32_t dst = bb + (uint32_t)pl*20480u + (uint32_t)(r*160 + j*16);
            uint32_t sz  = ok ? 16u : 0u;
            asm volatile("cp.async.cg.shared.global [%0], [%1], 16, %2;"
                         :: "r"(dst), "l"(src), "r"(sz));
        }
        // W planes: 2560 chunks (hi 1280 + lo 1280), linear copy
#pragma unroll
        for (int q = 0; q < 10; q++) {
            int cid = q*256 + tid;
            int pl  = cid >= 1280;
            int c   = pl ? cid - 1280 : cid;
            const float* base = pl ? g_w2l : g_w2h;
            const char* src = (const char*)(base + it*5120 + c*4);
            uint32_t dst = bb + 40960u + (uint32_t)pl*20480u + (uint32_t)(c*16);
            asm volatile("cp.async.cg.shared.global [%0], [%1], 16;"
                         :: "r"(dst), "l"(src));
        }
        asm volatile("cp.async.commit_group;");
    };

    issue(0, 0);

    const int m0 = (wid >> 2)*64, n0 = (wid & 3)*32;
    const int lr = lane >> 2, lc = lane & 3;
    const uint32_t aoff = (uint32_t)((m0 + lr)*160 + lc*8);
    const uint32_t boff = (uint32_t)((n0 + lr)*160 + lc*8);

    float acc[4][4][4];
#pragma unroll
    for (int mt = 0; mt < 4; mt++)
#pragma unroll
        for (int nt = 0; nt < 4; nt++)
#pragma unroll
            for (int c = 0; c < 4; c++) acc[mt][nt][c] = 0.f;

    for (int it = 0; it < 36; ++it) {
        if (it < 35) {
            issue(it + 1, (it + 1) & 1);
            asm volatile("cp.async.wait_group 1;");
        } else {
            asm volatile("cp.async.wait_group 0;");
        }
        __syncthreads();

        const uint32_t A0 = (uint32_t)((it & 1)*STG);
#pragma unroll
        for (int kk = 0; kk < 4; kk++) {
            const uint32_t kb = (uint32_t)(kk*32);
            float2 bh[4], bl[4];
#pragma unroll
            for (int nt = 0; nt < 4; nt++) {
                uint32_t ro = A0 + 40960u + boff + (uint32_t)(nt*8*160) + kb;
                bh[nt] = *(const float2*)(smem + ro);
                bl[nt] = *(const float2*)(smem + ro + 20480u);
            }
#pragma unroll
            for (int mt = 0; mt < 4; mt++) {
                uint32_t ro = A0 + aoff + (uint32_t)(mt*16*160) + kb;
                float2 h0 = *(const float2*)(smem + ro);
                float2 h1 = *(const float2*)(smem + ro + 8*160);
                float2 l0 = *(const float2*)(smem + ro + 20480u);
                float2 l1 = *(const float2*)(smem + ro + 20480u + 8*160);
                uint32_t ah[4] = {__float_as_uint(h0.x), __float_as_uint(h1.x),
                                  __float_as_uint(h0.y), __float_as_uint(h1.y)};
                uint32_t al[4] = {__float_as_uint(l0.x), __float_as_uint(l1.x),
                                  __float_as_uint(l0.y), __float_as_uint(l1.y)};
#pragma unroll
                for (int nt = 0; nt < 4; nt++) {
                    uint32_t b0h = __float_as_uint(bh[nt].x), b1h = __float_as_uint(bh[nt].y);
                    uint32_t b0l = __float_as_uint(bl[nt].x), b1l = __float_as_uint(bl[nt].y);
                    mma_tf32(acc[mt][nt], ah, b0h, b1h);
                    mma_tf32(acc[mt][nt], al, b0h, b1h);
                    mma_tf32(acc[mt][nt], ah, b0l, b1l);
                }
            }
        }
        __syncthreads();
    }

    // ---- epilogue: bias + ReLU -> smem [128 pos][132], then 4x4 pool -------
    float* sout = (float*)smem;
    const float* sbias = (const float*)(smem + OFF_BIAS);
#pragma unroll
    for (int mt = 0; mt < 4; mt++)
#pragma unroll
        for (int nt = 0; nt < 4; nt++) {
            int row = m0 + mt*16 + lr;
            int col = n0 + nt*8 + 2*lc;
            float b0 = sbias[col], b1 = sbias[col + 1];
            float v0 = acc[mt][nt][0] + b0, v1 = acc[mt][nt][1] + b1;
            float v2 = acc[mt][nt][2] + b0, v3 = acc[mt][nt][3] + b1;
            float2* p0 = (float2*)&sout[row*132 + col];
            float2* p1 = (float2*)&sout[(row + 8)*132 + col];
            *p0 = make_float2(v0 > 0.f ? v0 : 0.f, v1 > 0.f ? v1 : 0.f);
            *p1 = make_float2(v2 > 0.f ? v2 : 0.f, v3 > 0.f ? v3 : 0.f);
        }
    __syncthreads();

#pragma unroll
    for (int q = 0; q < 4; q++) {
        int id = q*256 + tid;          // 1024 outputs: 8 gw x 128 oc
        int gw = id >> 7, oc = id & 127;
        float s = 0.f;
#pragma unroll
        for (int oyl = 0; oyl < 4; oyl++)
#pragma unroll
            for (int i = 0; i < 4; i++)
                s += sout[(oyl*32 + gw*4 + i)*132 + oc];
        g_pool[(b*64 + g*8 + gw)*128 + oc] = s * (1.f/16.f);
    }
}

// ---------------- proj + VQ + dproj fused, one block per grid cell ----------
__global__ __launch_bounds__(128) void projvq_kernel(
    const float* __restrict__ proj_w, const float* __restrict__ proj_b,
    const float* __restrict__ cb,
    const float* __restrict__ dproj_w, const float* __restrict__ dproj_b,
    float* __restrict__ out)
{
    int n = blockIdx.x;
    int b = n >> 6, gh = (n >> 3) & 7, gw = n & 7;
    int tid = threadIdx.x;
    __shared__ float s_pool[128];
    __shared__ float z[64];
    __shared__ float zq[64];
    __shared__ float red[128];
    __shared__ int   redi[128];

    s_pool[tid] = g_pool[n*128 + tid];
    __syncthreads();

    if (tid < 64) {
        float s = proj_b[tid];
        const float4* pw4 = reinterpret_cast<const float4*>(&proj_w[tid*128]);
#pragma unroll 8
        for (int c4 = 0; c4 < 32; c4++) {
            float4 wv = pw4[c4];
            s = fmaf(wv.x, s_pool[4*c4 + 0], s);
            s = fmaf(wv.y, s_pool[4*c4 + 1], s);
            s = fmaf(wv.z, s_pool[4*c4 + 2], s);
            s = fmaf(wv.w, s_pool[4*c4 + 3], s);
        }
        z[tid] = s;
        out[ZE_OFF + ((b*64 + tid)*8 + gh)*8 + gw] = s;
    }
    __syncthreads();

    float best = FLT_MAX; int bi = 0;
    for (int kk = 0; kk < 4; kk++) {
        int k = tid*4 + kk;
        const float4* ck4 = reinterpret_cast<const float4*>(&cb[k*64]);
        float d2 = 0.f;
#pragma unroll
        for (int q = 0; q < 16; q++) {
            float4 cv = ck4[q];
            float d0 = z[4*q + 0] - cv.x; d2 = fmaf(d0, d0, d2);
            float d1 = z[4*q + 1] - cv.y; d2 = fmaf(d1, d1, d2);
            float d3 = z[4*q + 2] - cv.z; d2 = fmaf(d3, d3, d2);
            float d4 = z[4*q + 3] - cv.w; d2 = fmaf(d4, d4, d2);
        }
        if (d2 < best) { best = d2; bi = k; }
    }
    red[tid] = best; redi[tid] = bi;
    __syncthreads();
    for (int s = 64; s > 0; s >>= 1) {
        if (tid < s) {
            float d2 = red[tid + s]; int k2 = redi[tid + s];
            if (d2 < red[tid] || (d2 == red[tid] && k2 < redi[tid])) {
                red[tid] = d2; redi[tid] = k2;
            }
        }
        __syncthreads();
    }
    int idx = redi[0];
    if (tid == 0) out[IDX_OFF + n] = (float)idx;
    if (tid < 64) zq[tid] = cb[idx*64 + tid];
    __syncthreads();

    if (tid < 64) { float df = zq[tid] - z[tid]; red[tid] = df*df; }
    __syncthreads();
    if (tid < 32) red[tid] += red[tid + 32];  __syncthreads();
    if (tid < 16) red[tid] += red[tid + 16];  __syncthreads();
    if (tid <  8) red[tid] += red[tid +  8];  __syncthreads();
    if (tid <  4) red[tid] += red[tid +  4];  __syncthreads();
    if (tid <  2) red[tid] += red[tid +  2];  __syncthreads();
    if (tid == 0) g_partial[n] = red[0] + red[1];

    float s2 = dproj_b[tid];
    const float4* dw4 = reinterpret_cast<const float4*>(&dproj_w[tid*64]);
#pragma unroll
    for (int q = 0; q < 16; q++) {
        float4 wv = dw4[q];
        s2 = fmaf(wv.x, zq[4*q + 0], s2);
        s2 = fmaf(wv.y, zq[4*q + 1], s2);
        s2 = fmaf(wv.z, zq[4*q + 2], s2);
        s2 = fmaf(wv.w, zq[4*q + 3], s2);
    }
    g_v[n*128 + tid] = s2 > 0.f ? s2 : 0.f;
}

// ---------------- loss reduce -----------------------------------------------
__global__ void loss_kernel(float* __restrict__ out)
{
    __shared__ float s[1024];
    int t = threadIdx.x;
    s[t] = g_partial[t] + g_partial[t + 1024];
    __syncthreads();
    for (int k = 512; k > 0; k >>= 1) {
        if (t < k) s[t] += s[t + k];
        __syncthreads();
    }
    if (t == 0) out[LOSS_OFF] = 1.25f * s[0] / (2048.f * 64.f);
}

// ---------------- decoder: block-structured dconv1 + ReLU + dconv2 ----------
__global__ __launch_bounds__(128) void dec_kernel(
    const float* __restrict__ b1, const float* __restrict__ w2,
    const float* __restrict__ b2, float* __restrict__ out)
{
    int n0  = blockIdx.x * 4;
    int tid = threadIdx.x;
    __shared__ float s_comb[4][9][128];
    __shared__ float s_hcat[4][9][128];
    __shared__ float s_rgb[4][27];

#pragma unroll
    for (int cell = 0; cell < 4; cell++) {
        int n = n0 + cell;
        int gh = (n >> 3) & 7, gw = n & 7;
        float v00 = g_v[n*128 + tid];
        float va  = gh > 0             ? g_v[(n-8)*128 + tid] : 0.f;
        float vb  = gh < 7             ? g_v[(n+8)*128 + tid] : 0.f;
        float vl  = gw > 0             ? g_v[(n-1)*128 + tid] : 0.f;
        float vr  = gw < 7             ? g_v[(n+1)*128 + tid] : 0.f;
        float vtl = (gh > 0 && gw > 0) ? g_v[(n-9)*128 + tid] : 0.f;
        float vtr = (gh > 0 && gw < 7) ? g_v[(n-7)*128 + tid] : 0.f;
        float vbl = (gh < 7 && gw > 0) ? g_v[(n+7)*128 + tid] : 0.f;
        float vbr = (gh < 7 && gw < 7) ? g_v[(n+9)*128 + tid] : 0.f;

        s_comb[cell][0][tid] = v00;
        s_comb[cell][1][tid] = va - v00;
        s_comb[cell][2][tid] = vb - v00;
        s_comb[cell][3][tid] = vl - v00;
        s_comb[cell][4][tid] = vr - v00;
        s_comb[cell][5][tid] = vtl - va - vl + v00;
        s_comb[cell][6][tid] = vtr - va - vr + v00;
        s_comb[cell][7][tid] = vbl - vb - vl + v00;
        s_comb[cell][8][tid] = vbr - vb - vr + v00;
    }
    __syncthreads();

    float a[4][9];
#pragma unroll
    for (int cell = 0; cell < 4; cell++)
#pragma unroll
        for (int m = 0; m < 9; m++) a[cell][m] = 0.f;

    for (int ic = 0; ic < 128; ic++) {
#pragma unroll
        for (int m = 0; m < 9; m++) {
            float wv = g_wprep[(m*128 + ic)*128 + tid];
#pragma unroll
            for (int cell = 0; cell < 4; cell++)
                a[cell][m] = fmaf(wv, s_comb[cell][m][ic], a[cell][m]);
        }
    }

    float bv = b1[tid];
#pragma unroll
    for (int cell = 0; cell < 4; cell++) {
        float base = a[cell][0] + bv;
        float hm[9];
        hm[4] = base;
        hm[1] = base + a[cell][1];
        hm[7] = base + a[cell][2];
        hm[3] = base + a[cell][3];
        hm[5] = base + a[cell][4];
        hm[0] = base + a[cell][1] + a[cell][3] + a[cell][5];
        hm[2] = base + a[cell][1] + a[cell][4] + a[cell][6];
        hm[6] = base + a[cell][2] + a[cell][3] + a[cell][7];
        hm[8] = base + a[cell][2] + a[cell][4] + a[cell][8];
#pragma unroll
        for (int c = 0; c < 9; c++)
            s_hcat[cell][c][tid] = hm[c] > 0.f ? hm[c] : 0.f;
    }
    __syncthreads();

    if (tid < 108) {
        int cell = tid / 27;
        int r    = tid % 27;
        int ch   = r / 9;
        int cat  = r % 9;
        const float4* wc4 = reinterpret_cast<const float4*>(&w2[ch*128]);
        const float*  hc  = &s_hcat[cell][cat][0];
        float s = 0.f;
#pragma unroll
        for (int q = 0; q < 32; q++) {
            float4 wv = wc4[q];
            s = fmaf(wv.x, hc[4*q + 0], s);
            s = fmaf(wv.y, hc[4*q + 1], s);
            s = fmaf(wv.z, hc[4*q + 2], s);
            s = fmaf(wv.w, hc[4*q + 3], s);
        }
        s_rgb[cell][r] = s + b2[ch];
    }
    __syncthreads();

    for (int p = tid; p < 3072; p += 128) {
        int cell = p / 768;
        int rem  = p % 768;
        int ch = rem >> 8, r = (rem >> 4) & 15, c = rem & 15;
        int n = n0 + cell;
        int b = n >> 6, gh = (n >> 3) & 7, gw = n & 7;
        int rcat = (r == 0) ? 0 : ((r == 15) ? 2 : 1);
        int ccat = (c == 0) ? 0 : ((c == 15) ? 2 : 1);
        out[XHAT_OFF + ((b*3 + ch)*128 + gh*16 + r)*128 + gw*16 + c]
            = s_rgb[cell][ch*9 + rcat*3 + ccat];
    }
}

// ---------------- launch ----------------------------------------------------
extern "C" void kernel_launch(void* const* d_in, const int* in_sizes, int n_in,
                              void* d_out, int out_size)
{
    const float* x        = (const float*)d_in[0];
    const float* enc_w1   = (const float*)d_in[1];
    const float* enc_b1   = (const float*)d_in[2];
    const float* enc_w2   = (const float*)d_in[3];
    const float* enc_b2   = (const float*)d_in[4];
    const float* proj_w   = (const float*)d_in[5];
    const float* proj_b   = (const float*)d_in[6];
    const float* codebook = (const float*)d_in[7];
    const float* dproj_w  = (const float*)d_in[8];
    const float* dproj_b  = (const float*)d_in[9];
    const float* dconv1_w = (const float*)d_in[10];
    const float* dconv1_b = (const float*)d_in[11];
    const float* dconv2_w = (const float*)d_in[12];
    const float* dconv2_b = (const float*)d_in[13];
    float* out = (float*)d_out;

    cudaFuncSetAttribute(conv2_mma_kernel,
                         cudaFuncAttributeMaxDynamicSharedMemorySize, 164352);

    conv1_kernel<<<dim3(2, 64, 32), 128>>>(x, enc_w1, enc_b1);
    prep_kernel<<<576, 256>>>(enc_w2, dconv1_w);
    conv2_mma_kernel<<<dim3(8, 32), 256, 164352>>>(enc_b2);
    projvq_kernel<<<2048, 128>>>(proj_w, proj_b, codebook, dproj_w, dproj_b, out);
    dec_kernel<<<512, 128>>>(dconv1_b, dconv2_w, dconv2_b, out);
    loss_kernel<<<1, 1024>>>(out);
}